// round 5
// baseline (speedup 1.0000x reference)
#include <cuda_runtime.h>
#include <cuda_fp16.h>
#include <cstdint>
#include <math.h>

#define NT     16
#define S_LEN  4096
#define B_SZ   512
#define CHUNK  8

// Per-row partial results (device globals: allocation-free scratch).
__device__ float g_fwd[B_SZ];
__device__ float g_gold[B_SZ];

__device__ __forceinline__ unsigned h2u(__half2 v) { return *reinterpret_cast<unsigned*>(&v); }
__device__ __forceinline__ __half2  u2h(unsigned v) { return *reinterpret_cast<__half2*>(&v); }

// Detect element strides (bytes) of tags/mask buffers (JAX dtype ambiguity).
__device__ __forceinline__ int detect_mask_stride(const unsigned char* mb) {
    return (mb[1] | mb[2] | mb[3]) ? 1 : 4;
}
__device__ __forceinline__ int detect_tag_stride(const void* tp) {
    const int* w = (const int*)tp;
    int nz = 0;
#pragma unroll
    for (int k = 0; k < 32; ++k) nz |= w[1 + 2 * k];   // high halves if int64
    return nz ? 4 : 8;
}

// One block = 96 threads = 3 warps, covering 4 batch rows.
//   warp 0: forward algorithm, 8 lanes/row (lane owns 2 tags, fp16x2 state)
//   warp 1: gold score rows 4b+0,4b+1 (16 lanes/row)
//   warp 2: gold score rows 4b+2,4b+3
__global__ void __launch_bounds__(96, 1) crf_main_kernel(
    const float* __restrict__ emissions,          // [B, S, NT] f32
    const void*  __restrict__ tags_raw,           // [B, S] i32 or i64
    const void*  __restrict__ mask_raw,           // [B, S] u8 or i32 (bool)
    const float* __restrict__ transitions,        // [NT, NT] f32
    const float* __restrict__ start_t,            // [NT] f32
    const float* __restrict__ end_t)              // [NT] f32
{
    const int warp = threadIdx.x >> 5;
    const int lane = threadIdx.x & 31;

    const unsigned char* mask_b = (const unsigned char*)mask_raw;
    const unsigned char* tags_b = (const unsigned char*)tags_raw;
    const int mstride = detect_mask_stride(mask_b);

    if (warp == 0) {
        // ---------------- forward algorithm (fp16 linear space, per-step 2^-k rescale)
        const int r   = lane >> 3;                 // row within warp (0..3)
        const int h   = lane & 7;                  // owns tags 2h, 2h+1
        const int row = blockIdx.x * 4 + r;
        const int j0  = 2 * h, j1 = 2 * h + 1;

        // Packed fp16 transition constants:
        //   P[i] = (eT[2i][j0],   eT[2i+1][j1])   pairs with g_i = (s[2i], s[2i+1])
        //   Q[i] = (eT[2i+1][j0], eT[2i][j1])     pairs with swap(g_i)
        unsigned P[8], Q[8];
#pragma unroll
        for (int i = 0; i < 8; ++i) {
            const float a = __expf(transitions[(2 * i)     * NT + j0]);
            const float b = __expf(transitions[(2 * i + 1) * NT + j1]);
            const float c = __expf(transitions[(2 * i + 1) * NT + j0]);
            const float d = __expf(transitions[(2 * i)     * NT + j1]);
            P[i] = h2u(__floats2half2_rn(a, b));
            Q[i] = h2u(__floats2half2_rn(c, d));
        }

        const float2* erow2 =
            reinterpret_cast<const float2*>(emissions + (size_t)row * S_LEN * NT) + h;
        const unsigned char* mrow = mask_b + (size_t)row * S_LEN * mstride;

        // init: s_j = exp(start_j + e0_j), packed fp16
        const float2 e00 = erow2[0];
        unsigned sp = h2u(__floats2half2_rn(__expf(start_t[j0] + e00.x),
                                            __expf(start_t[j1] + e00.y)));
        int ksum = 0;

        // register prefetch pipeline
        float2 ebuf[CHUNK];
        int    mbuf[CHUNK];
#pragma unroll
        for (int p = 0; p < CHUNK; ++p) {
            ebuf[p] = erow2[(size_t)p * 8];
            mbuf[p] = mrow[(size_t)p * mstride];
        }

        for (int tb = 0; tb < S_LEN; tb += CHUNK) {
#pragma unroll
            for (int u = 0; u < CHUNK; ++u) {
                const int t = tb + u;
                const float2 e = ebuf[u];
                const int    m = (t == 0) ? 0 : mbuf[u];  // step 0 is the init

                const int tp = t + CHUNK;
                if (tp < S_LEN) {
                    ebuf[u] = erow2[(size_t)tp * 8];
                    mbuf[u] = mrow[(size_t)tp * mstride];
                }

                // gather 16 fp16 states with 8 shfls (width 8 = own row group)
                unsigned gi[8];
#pragma unroll
                for (int i = 0; i < 8; ++i)
                    gi[i] = __shfl_sync(0xffffffffu, sp, i, 8);

                // branchless per-step rescale from s0's fp16 exponent; target s0~2^-6
                const int ef = (gi[0] >> 10) & 0x1f;
                int kcur = ef - 9;
                kcur = (kcur < -8) ? -8 : kcur;           // scale <= 2^8 (no fp16 ovf)
                const float scalef = __uint_as_float((unsigned)(127 - kcur) << 23);

                // dot in half2: acc = (sum_k s_k*eT[k][j0], sum_k s_k*eT[k][j1])
                __half2 a0 = __hmul2(u2h(gi[0]), u2h(P[0]));
                a0 = __hfma2(__lowhigh2highlow(u2h(gi[0])), u2h(Q[0]), a0);
                a0 = __hfma2(u2h(gi[4]), u2h(P[4]), a0);
                a0 = __hfma2(__lowhigh2highlow(u2h(gi[4])), u2h(Q[4]), a0);

                __half2 a1 = __hmul2(u2h(gi[1]), u2h(P[1]));
                a1 = __hfma2(__lowhigh2highlow(u2h(gi[1])), u2h(Q[1]), a1);
                a1 = __hfma2(u2h(gi[5]), u2h(P[5]), a1);
                a1 = __hfma2(__lowhigh2highlow(u2h(gi[5])), u2h(Q[5]), a1);

                __half2 a2 = __hmul2(u2h(gi[2]), u2h(P[2]));
                a2 = __hfma2(__lowhigh2highlow(u2h(gi[2])), u2h(Q[2]), a2);
                a2 = __hfma2(u2h(gi[6]), u2h(P[6]), a2);
                a2 = __hfma2(__lowhigh2highlow(u2h(gi[6])), u2h(Q[6]), a2);

                __half2 a3 = __hmul2(u2h(gi[3]), u2h(P[3]));
                a3 = __hfma2(__lowhigh2highlow(u2h(gi[3])), u2h(Q[3]), a3);
                a3 = __hfma2(u2h(gi[7]), u2h(P[7]), a3);
                a3 = __hfma2(__lowhigh2highlow(u2h(gi[7])), u2h(Q[7]), a3);

                const __half2 acc = __hadd2(__hadd2(a0, a1), __hadd2(a2, a3));

                // emission weight * scale (fp32 -> fp16x2), then update + select
                const float  w0 = __expf(e.x) * scalef;
                const float  w1 = __expf(e.y) * scalef;
                const __half2 w2 = __floats2half2_rn(w0, w1);
                const unsigned nsu = h2u(__hmul2(acc, w2));

                sp    = m ? nsu : sp;
                ksum += m ? kcur : 0;
            }
        }

        // forward_score = log(sum_j s_j * exp(end_j)) + ksum*ln2
        const float2 cf = __half22float2(u2h(sp));
        float rsum = cf.x * __expf(end_t[j0]) + cf.y * __expf(end_t[j1]);
#pragma unroll
        for (int off = 4; off >= 1; off >>= 1)
            rsum += __shfl_xor_sync(0xffffffffu, rsum, off, 8);
        if (h == 0)
            g_fwd[row] = logf(rsum) + (float)ksum * 0.6931471805599453f;
    } else {
        // ---------------- gold path score (fp32 exact) ----------------
        const int j   = lane & 15;
        const int row = blockIdx.x * 4 + (warp - 1) * 2 + (lane >> 4);

        const int tstride = detect_tag_stride(tags_raw);
        const unsigned char* trow = tags_b + (size_t)row * S_LEN * tstride;
        const unsigned char* mrow = mask_b + (size_t)row * S_LEN * mstride;
        const float*         erow = emissions + (size_t)row * S_LEN * NT;

        float acc = 0.0f;
        int   cnt = 0;
        for (int t = j; t < S_LEN; t += 16) {
            const int tg = trow[(size_t)t * tstride];       // tag fits in 1 byte
            const int mm = mrow[(size_t)t * mstride];
            cnt += mm ? 1 : 0;
            if (t == 0) {
                acc += start_t[tg] + erow[tg];
            } else if (mm) {
                const int tpv = trow[(size_t)(t - 1) * tstride];
                acc += transitions[tpv * NT + tg] + erow[(size_t)t * NT + tg];
            }
        }
#pragma unroll
        for (int off = 8; off >= 1; off >>= 1) {
            acc += __shfl_xor_sync(0xffffffffu, acc, off, 16);
            cnt += __shfl_xor_sync(0xffffffffu, cnt, off, 16);
        }
        if (j == 0) {
            int last = cnt - 1;
            if (last < 0) last = 0;                 // safety (all-false mask)
            const int lt = trow[(size_t)last * tstride];
            g_gold[row] = acc + end_t[lt];
        }
    }
}

__global__ void crf_reduce_kernel(float* __restrict__ out)
{
    __shared__ float sh[B_SZ];
    const int i = threadIdx.x;
    sh[i] = g_fwd[i] - g_gold[i];
    __syncthreads();
#pragma unroll
    for (int s2 = B_SZ / 2; s2 > 0; s2 >>= 1) {
        if (i < s2) sh[i] += sh[i + s2];
        __syncthreads();
    }
    if (i == 0) out[0] = sh[0] * (1.0f / (float)B_SZ);
}

extern "C" void kernel_launch(void* const* d_in, const int* in_sizes, int n_in,
                              void* d_out, int out_size)
{
    (void)in_sizes; (void)n_in; (void)out_size;
    const float* emissions   = (const float*)d_in[0];
    const void*  tags        = d_in[1];
    const void*  mask        = d_in[2];
    const float* transitions = (const float*)d_in[3];
    const float* start_t     = (const float*)d_in[4];
    const float* end_t       = (const float*)d_in[5];

    crf_main_kernel<<<B_SZ / 4, 96>>>(emissions, tags, mask, transitions, start_t, end_t);
    crf_reduce_kernel<<<1, B_SZ>>>((float*)d_out);
}

// round 6
// speedup vs baseline: 2.4907x; 2.4907x over previous
#include <cuda_runtime.h>
#include <cstdint>
#include <math.h>

#define NT     16
#define S_LEN  4096
#define B_SZ   512
#define CHUNK  8
#define NBLK   (B_SZ / 2)

// Per-row partial results + completion counter (device globals: legal scratch).
__device__ float g_fwd[B_SZ];
__device__ float g_gold[B_SZ];
__device__ unsigned g_done = 0;

// ---- volatile smem helpers (plain STS/LDS.128, ordering guaranteed) ----
__device__ __forceinline__ unsigned smem_addr(const void* p) {
    unsigned a;
    asm("{ .reg .u64 t; cvta.to.shared.u64 t, %1; cvt.u32.u64 %0, t; }"
        : "=r"(a) : "l"(p));
    return a;
}
__device__ __forceinline__ void sts32v(unsigned addr, float v) {
    asm volatile("st.volatile.shared.f32 [%0], %1;" :: "r"(addr), "f"(v));
}
__device__ __forceinline__ float4 lds128v(unsigned addr) {
    float4 r;
    asm volatile("ld.volatile.shared.v4.f32 {%0,%1,%2,%3}, [%4];"
                 : "=f"(r.x), "=f"(r.y), "=f"(r.z), "=f"(r.w) : "r"(addr));
    return r;
}

// Detect element strides (bytes) of tags/mask buffers (JAX dtype ambiguity).
__device__ __forceinline__ int detect_mask_stride(const unsigned char* mb) {
    return (mb[1] | mb[2] | mb[3]) ? 1 : 4;
}
__device__ __forceinline__ int detect_tag_stride(const void* tp) {
    const int* w = (const int*)tp;
    int nz = 0;
#pragma unroll
    for (int k = 0; k < 32; ++k) nz |= w[1 + 2 * k];   // high halves if int64
    return nz ? 4 : 8;
}

// One block = 64 threads = 2 warps, 2 batch rows.
//   warp 0: forward algorithm (16 lanes/row), smem ping-pong state transport
//   warp 1: gold path score (16 lanes/row)
// Last block to finish reduces g_fwd - g_gold into out.
__global__ void __launch_bounds__(64, 1) crf_fused_kernel(
    const float* __restrict__ emissions,          // [B, S, NT] f32
    const void*  __restrict__ tags_raw,           // [B, S] i32 or i64
    const void*  __restrict__ mask_raw,           // [B, S] u8 or i32 (bool)
    const float* __restrict__ transitions,        // [NT, NT] f32
    const float* __restrict__ start_t,            // [NT] f32
    const float* __restrict__ end_t,              // [NT] f32
    float* __restrict__ out)
{
    const int warp = threadIdx.x >> 5;
    const int lane = threadIdx.x & 31;
    const int j    = lane & 15;                  // tag index
    const int r    = lane >> 4;                  // row-within-warp (0/1)
    const int row  = blockIdx.x * 2 + r;

    const unsigned char* mask_b = (const unsigned char*)mask_raw;
    const unsigned char* tags_b = (const unsigned char*)tags_raw;
    const int mstride = detect_mask_stride(mask_b);

    // ping-pong state: [parity][rowInWarp][tag] (warp-0 private; no sync needed)
    __shared__ float sbuf[2][2][NT];
    __shared__ int   s_last;

    if (warp == 0) {
        // ---------------- forward algorithm (fp32 linear space, 2^-k rescale) -----
        float eT[NT];
#pragma unroll
        for (int i = 0; i < NT; ++i) eT[i] = __expf(transitions[i * NT + j]);

        const float* erow = emissions + (size_t)row * S_LEN * NT + j;
        const unsigned char* mrow = mask_b + (size_t)row * S_LEN * mstride;

        float s = __expf(start_t[j] + erow[0]);
        int   ksum = 0;

        const unsigned sb    = smem_addr(&sbuf[0][0][0]);
        const unsigned rbase = sb + (unsigned)(r * 64);
        unsigned par = 0;                         // byte offset of current parity

        sts32v(rbase + par + (unsigned)(j * 4), s);   // publish init (parity 0)

        // register prefetch pipeline
        float ebuf[CHUNK];
        int   mbuf[CHUNK];
#pragma unroll
        for (int p = 0; p < CHUNK; ++p) {
            ebuf[p] = erow[(size_t)p * NT];
            mbuf[p] = mrow[(size_t)p * mstride];
        }

        for (int tb = 0; tb < S_LEN; tb += CHUNK) {
#pragma unroll
            for (int u = 0; u < CHUNK; ++u) {
                const int t = tb + u;
                const float e = ebuf[u];
                const int   m = (t == 0) ? 0 : mbuf[u];

                const int tp = t + CHUNK;
                if (tp < S_LEN) {
                    ebuf[u] = erow[(size_t)tp * NT];
                    mbuf[u] = mrow[(size_t)tp * mstride];
                }

                // gather state: 4x LDS.128 broadcast (conflict-free, same warp)
                const unsigned ra = rbase + par;
                const float4 v0 = lds128v(ra);
                const float4 v1 = lds128v(ra + 16);
                const float4 v2 = lds128v(ra + 32);
                const float4 v3 = lds128v(ra + 48);

                // per-step rescale from v0.x's exponent (exact 2^-k, off-chain)
                const unsigned ub = __float_as_uint(v0.x);
                const int ef = (int)((ub >> 23) & 0xffu);
                int   kcur;
                float scale;
                if (ef >= 1 && ef <= 253) {
                    kcur  = ef - 127;
                    scale = __uint_as_float((unsigned)(254 - ef) << 23);
                } else {
                    kcur = 0; scale = 1.0f;
                }

                // dot(state, eT): balanced tree
                const float p0 = fmaf(v0.y, eT[1],  v0.x * eT[0]);
                const float p1 = fmaf(v0.w, eT[3],  v0.z * eT[2]);
                const float p2 = fmaf(v1.y, eT[5],  v1.x * eT[4]);
                const float p3 = fmaf(v1.w, eT[7],  v1.z * eT[6]);
                const float p4 = fmaf(v2.y, eT[9],  v2.x * eT[8]);
                const float p5 = fmaf(v2.w, eT[11], v2.z * eT[10]);
                const float p6 = fmaf(v3.y, eT[13], v3.x * eT[12]);
                const float p7 = fmaf(v3.w, eT[15], v3.z * eT[14]);
                const float a0 = p0 + p1, a1 = p2 + p3, a2 = p4 + p5, a3 = p6 + p7;
                const float acc = (a0 + a1) + (a2 + a3);

                const float w  = __expf(e) * scale;   // off-chain (e prefetched)
                const float ns = acc * w;
                s    = m ? ns : s;
                ksum += m ? kcur : 0;

                // publish to other parity (same warp: program order suffices)
                par ^= 128u;
                sts32v(rbase + par + (unsigned)(j * 4), s);
            }
        }

        float rsum = s * __expf(end_t[j]);
#pragma unroll
        for (int off = 8; off >= 1; off >>= 1)
            rsum += __shfl_xor_sync(0xffffffffu, rsum, off, 16);
        if (j == 0)
            g_fwd[row] = logf(rsum) + (float)ksum * 0.6931471805599453f;
    } else {
        // ---------------- gold path score (fp32 exact) ----------------
        const int tstride = detect_tag_stride(tags_raw);
        const unsigned char* trow = tags_b + (size_t)row * S_LEN * tstride;
        const unsigned char* mrow = mask_b + (size_t)row * S_LEN * mstride;
        const float*         erow = emissions + (size_t)row * S_LEN * NT;

        float acc = 0.0f;
        int   cnt = 0;
        for (int t = j; t < S_LEN; t += 16) {
            const int tg = trow[(size_t)t * tstride];
            const int mm = mrow[(size_t)t * mstride];
            cnt += mm ? 1 : 0;
            if (t == 0) {
                acc += start_t[tg] + erow[tg];
            } else if (mm) {
                const int tpv = trow[(size_t)(t - 1) * tstride];
                acc += transitions[tpv * NT + tg] + erow[(size_t)t * NT + tg];
            }
        }
#pragma unroll
        for (int off = 8; off >= 1; off >>= 1) {
            acc += __shfl_xor_sync(0xffffffffu, acc, off, 16);
            cnt += __shfl_xor_sync(0xffffffffu, cnt, off, 16);
        }
        if (j == 0) {
            int last = cnt - 1;
            if (last < 0) last = 0;
            const int lt = trow[(size_t)last * tstride];
            g_gold[row] = acc + end_t[lt];
        }
    }

    // ---------------- last-block reduction ----------------
    __syncthreads();
    if (threadIdx.x == 0) {
        __threadfence();
        const unsigned old = atomicAdd(&g_done, 1u);
        s_last = (old == NBLK - 1u) ? 1 : 0;
    }
    __syncthreads();
    if (s_last) {
        __threadfence();
        float a = 0.0f;
        for (int i = threadIdx.x; i < B_SZ; i += 64)
            a += g_fwd[i] - g_gold[i];
#pragma unroll
        for (int off = 16; off >= 1; off >>= 1)
            a += __shfl_xor_sync(0xffffffffu, a, off);
        __shared__ float wsum[2];
        if ((threadIdx.x & 31) == 0) wsum[threadIdx.x >> 5] = a;
        __syncthreads();
        if (threadIdx.x == 0) {
            out[0] = (wsum[0] + wsum[1]) * (1.0f / (float)B_SZ);
            g_done = 0;                      // reset for next graph replay
        }
    }
}

extern "C" void kernel_launch(void* const* d_in, const int* in_sizes, int n_in,
                              void* d_out, int out_size)
{
    (void)in_sizes; (void)n_in; (void)out_size;
    const float* emissions   = (const float*)d_in[0];
    const void*  tags        = d_in[1];
    const void*  mask        = d_in[2];
    const float* transitions = (const float*)d_in[3];
    const float* start_t     = (const float*)d_in[4];
    const float* end_t       = (const float*)d_in[5];

    crf_fused_kernel<<<NBLK, 64>>>(emissions, tags, mask, transitions,
                                   start_t, end_t, (float*)d_out);
}